// round 1
// baseline (speedup 1.0000x reference)
#include <cuda_runtime.h>
#include <math.h>

// ---------------- problem constants ----------------
#define BB     16
#define NTOK   1569
#define DIM    768
#define NH     12
#define HD     64
#define NF     8
#define NS     196          // (NTOK-1)/NF
#define ROWS   (BB * NTOK)  // 25104
#define QKVD   (3 * DIM)    // 2304
#define MLPD   (4 * DIM)    // 3072

// ---------------- scratch (device globals; no runtime alloc) ----------------
__device__ float g_ln [ (long)ROWS * DIM  ];
__device__ float g_qkv[ (long)ROWS * QKVD ];
__device__ float g_att[ (long)ROWS * DIM  ];
__device__ float g_h1 [ (long)ROWS * MLPD ];

// ---------------- helpers ----------------
__device__ __forceinline__ float gelu_tanh(float x) {
    // jax.nn.gelu default (approximate=True)
    float x3 = x * x * x;
    float t  = tanhf(0.7978845608028654f * (x + 0.044715f * x3));
    return 0.5f * x * (1.0f + t);
}

// ---------------- LayerNorm over last dim (768), 256 thr, 3 elems/thr ----------------
__global__ void ln_kernel(const float* __restrict__ x, const float* __restrict__ w,
                          const float* __restrict__ b, float* __restrict__ out) {
    long row = blockIdx.x;
    const float* xr = x + row * DIM;
    float* orow = out + row * DIM;
    int t = threadIdx.x;
    float v0 = xr[t], v1 = xr[t + 256], v2 = xr[t + 512];
    float s  = v0 + v1 + v2;
    float s2 = v0 * v0 + v1 * v1 + v2 * v2;
    #pragma unroll
    for (int o = 16; o > 0; o >>= 1) {
        s  += __shfl_xor_sync(0xffffffffu, s,  o);
        s2 += __shfl_xor_sync(0xffffffffu, s2, o);
    }
    __shared__ float sh[64];
    int wid = t >> 5, lane = t & 31;
    if (lane == 0) { sh[wid] = s; sh[32 + wid] = s2; }
    __syncthreads();
    float ts = 0.f, ts2 = 0.f;
    #pragma unroll
    for (int i = 0; i < 8; i++) { ts += sh[i]; ts2 += sh[32 + i]; }
    float mean = ts * (1.0f / DIM);
    float var  = ts2 * (1.0f / DIM) - mean * mean;
    float inv  = rsqrtf(var + 1e-6f);
    orow[t]       = (v0 - mean) * inv * w[t]       + b[t];
    orow[t + 256] = (v1 - mean) * inv * w[t + 256] + b[t + 256];
    orow[t + 512] = (v2 - mean) * inv * w[t + 512] + b[t + 512];
}

// ---------------- SGEMM: C[M,N] = A[M,K] @ W[K,N] + bias (+gelu) (+res) ----------------
// BM=BN=128, BK=8, 256 threads, 8x8 per-thread tile. N%128==0, K%8==0; only M ragged.
#define Bb_M 128
#define Bb_N 128
#define Bb_K 8
__global__ __launch_bounds__(256)
void gemm_kernel(const float* __restrict__ A, const float* __restrict__ W,
                 const float* __restrict__ bias, const float* __restrict__ res,
                 float* __restrict__ C, int M, int N, int K, int act) {
    __shared__ float As[Bb_K][Bb_M];
    __shared__ float Bs[Bb_K][Bb_N];
    int bx = blockIdx.x, by = blockIdx.y;
    int tid = threadIdx.x;
    int tx = tid & 15;         // N dir
    int ty = tid >> 4;         // M dir
    float acc[8][8];
    #pragma unroll
    for (int i = 0; i < 8; i++)
        #pragma unroll
        for (int j = 0; j < 8; j++) acc[i][j] = 0.f;

    int aRow = tid >> 1;            // 0..127
    int aCol = (tid & 1) * 4;       // 0 or 4
    int bRow = tid >> 5;            // 0..7
    int bCol = (tid & 31) * 4;      // 0..124
    const float* Ab = A + (long)by * Bb_M * K;
    const float* Wb = W + bx * Bb_N;
    bool aOk = (by * Bb_M + aRow) < M;

    for (int k0 = 0; k0 < K; k0 += Bb_K) {
        float4 av = aOk ? *(const float4*)(Ab + (long)aRow * K + k0 + aCol)
                        : make_float4(0.f, 0.f, 0.f, 0.f);
        As[aCol + 0][aRow] = av.x;
        As[aCol + 1][aRow] = av.y;
        As[aCol + 2][aRow] = av.z;
        As[aCol + 3][aRow] = av.w;
        float4 wv = *(const float4*)(Wb + (long)(k0 + bRow) * N + bCol);
        *(float4*)&Bs[bRow][bCol] = wv;
        __syncthreads();
        #pragma unroll
        for (int k = 0; k < Bb_K; ++k) {
            float ra[8], rb[8];
            #pragma unroll
            for (int i = 0; i < 8; i++) ra[i] = As[k][ty * 8 + i];
            #pragma unroll
            for (int j = 0; j < 8; j++) rb[j] = Bs[k][tx * 8 + j];
            #pragma unroll
            for (int i = 0; i < 8; i++)
                #pragma unroll
                for (int j = 0; j < 8; j++) acc[i][j] = fmaf(ra[i], rb[j], acc[i][j]);
        }
        __syncthreads();
    }

    long row0 = (long)by * Bb_M + ty * 8;
    int  col0 = bx * Bb_N + tx * 8;
    #pragma unroll
    for (int i = 0; i < 8; i++) {
        long r = row0 + i;
        if (r >= M) break;
        float* Crow = C + r * N;
        const float* Rrow = res ? res + r * N : nullptr;
        #pragma unroll
        for (int j = 0; j < 8; j++) {
            int c = col0 + j;
            float v = acc[i][j] + bias[c];
            if (act) v = gelu_tanh(v);
            if (Rrow) v += Rrow[c];
            Crow[c] = v;
        }
    }
}

// ---------------- time attention: per (b,h,n) block, 8 warps = 8 frame-queries, 9 keys ----------------
__global__ __launch_bounds__(256)
void time_attn_kernel(const float* __restrict__ qkv, float* __restrict__ att) {
    int blk = blockIdx.x;
    int n = blk % NS;
    int h = (blk / NS) % NH;
    int b = blk / (NS * NH);
    __shared__ float ks[9][HD], vs[9][HD];
    const float* base = qkv + (long)b * NTOK * QKVD;
    int qoff = h * HD;
    int t = threadIdx.x;
    for (int i = t; i < 9 * HD; i += 256) {
        int j = i / HD, dd = i % HD;
        int tok = (j == 0) ? 0 : 1 + (j - 1) * NS + n;
        const float* row = base + (long)tok * QKVD;
        ks[j][dd] = row[DIM + qoff + dd];
        vs[j][dd] = row[2 * DIM + qoff + dd];
    }
    __syncthreads();
    int f = t >> 5, lane = t & 31;
    int qtok = 1 + f * NS + n;
    const float* qrow = base + (long)qtok * QKVD + qoff;
    float q0 = qrow[lane], q1 = qrow[lane + 32];
    float sc[9];
    #pragma unroll
    for (int j = 0; j < 9; j++) {
        float p = q0 * ks[j][lane] + q1 * ks[j][lane + 32];
        #pragma unroll
        for (int o = 16; o > 0; o >>= 1) p += __shfl_xor_sync(0xffffffffu, p, o);
        sc[j] = p * 0.125f;
    }
    float m = sc[0];
    #pragma unroll
    for (int j = 1; j < 9; j++) m = fmaxf(m, sc[j]);
    float l = 0.f;
    #pragma unroll
    for (int j = 0; j < 9; j++) { sc[j] = expf(sc[j] - m); l += sc[j]; }
    float inv = 1.0f / l;
    float o0 = 0.f, o1 = 0.f;
    #pragma unroll
    for (int j = 0; j < 9; j++) {
        o0 = fmaf(sc[j], vs[j][lane], o0);
        o1 = fmaf(sc[j], vs[j][lane + 32], o1);
    }
    float* orow = att + (long)b * NTOK * DIM + (long)qtok * DIM + h * HD;
    orow[lane]      = o0 * inv;
    orow[lane + 32] = o1 * inv;
}

// ---------------- space attention: per (b,h,f) block; 196 queries x 197 keys ----------------
#define SP_KV_PAD 65
#define SP_KS_OFF 0
#define SP_VS_OFF (197 * SP_KV_PAD)
#define SP_P_OFF  (2 * 197 * SP_KV_PAD)
#define SP_Q_OFF  (SP_P_OFF + 8 * 200)
#define SP_SMEM_FLOATS (SP_Q_OFF + 8 * 64)
#define SP_SMEM_BYTES (SP_SMEM_FLOATS * 4)

__global__ __launch_bounds__(256)
void space_attn_kernel(const float* __restrict__ qkv, float* __restrict__ att) {
    extern __shared__ float sm[];
    float* Ks = sm + SP_KS_OFF;
    float* Vs = sm + SP_VS_OFF;
    int blk = blockIdx.x;
    int f = blk % NF;
    int h = (blk / NF) % NH;
    int b = blk / (NF * NH);
    const float* base = qkv + (long)b * NTOK * QKVD;
    int qoff = h * HD;
    int t = threadIdx.x;
    for (int i = t; i < 197 * HD; i += 256) {
        int j = i / HD, dd = i % HD;
        int tok = (j == 0) ? 0 : 1 + f * NS + (j - 1);
        const float* row = base + (long)tok * QKVD;
        Ks[j * SP_KV_PAD + dd] = row[DIM + qoff + dd];
        Vs[j * SP_KV_PAD + dd] = row[2 * DIM + qoff + dd];
    }
    __syncthreads();
    int w = t >> 5, lane = t & 31;
    float* p  = sm + SP_P_OFF + w * 200;
    float* qs = sm + SP_Q_OFF + w * 64;
    for (int n = w; n < NS; n += 8) {
        int qtok = 1 + f * NS + n;
        const float* qrow = base + (long)qtok * QKVD + qoff;
        qs[lane]      = qrow[lane];
        qs[lane + 32] = qrow[lane + 32];
        __syncwarp();
        float s[7];
        float mloc = -1e30f;
        #pragma unroll
        for (int kk = 0; kk < 7; kk++) {
            int j = lane + kk * 32;
            float a = -1e30f;
            if (j < 197) {
                a = 0.f;
                const float* kr = Ks + j * SP_KV_PAD;
                #pragma unroll
                for (int dd = 0; dd < HD; dd++) a = fmaf(qs[dd], kr[dd], a);
                a *= 0.125f;
            }
            s[kk] = a;
            mloc = fmaxf(mloc, a);
        }
        #pragma unroll
        for (int o = 16; o > 0; o >>= 1) mloc = fmaxf(mloc, __shfl_xor_sync(0xffffffffu, mloc, o));
        float lsum = 0.f;
        #pragma unroll
        for (int kk = 0; kk < 7; kk++) {
            int j = lane + kk * 32;
            if (j < 197) { s[kk] = expf(s[kk] - mloc); lsum += s[kk]; }
        }
        #pragma unroll
        for (int o = 16; o > 0; o >>= 1) lsum += __shfl_xor_sync(0xffffffffu, lsum, o);
        float inv = 1.0f / lsum;
        #pragma unroll
        for (int kk = 0; kk < 7; kk++) {
            int j = lane + kk * 32;
            if (j < 197) p[j] = s[kk] * inv;
        }
        __syncwarp();
        float o0 = 0.f, o1 = 0.f;
        for (int j = 0; j < 197; j++) {
            float pj = p[j];
            o0 = fmaf(pj, Vs[j * SP_KV_PAD + lane], o0);
            o1 = fmaf(pj, Vs[j * SP_KV_PAD + lane + 32], o1);
        }
        float* orow = att + (long)b * NTOK * DIM + (long)qtok * DIM + h * HD;
        orow[lane]      = o0;
        orow[lane + 32] = o1;
        __syncwarp();
    }
}

// ---------------- cls attention: per (b,h); 1 query over all 1569 keys ----------------
__global__ __launch_bounds__(256)
void cls_attn_kernel(const float* __restrict__ qkv, float* __restrict__ att) {
    int h = blockIdx.x % NH;
    int b = blockIdx.x / NH;
    const float* base = qkv + (long)b * NTOK * QKVD;
    __shared__ float qsm[HD];
    __shared__ float sc[NTOK];
    __shared__ float red[32];
    __shared__ float part[4 * HD];
    int t = threadIdx.x;
    if (t < HD) qsm[t] = base[h * HD + t];
    __syncthreads();
    float mloc = -1e30f;
    for (int j = t; j < NTOK; j += 256) {
        const float* kr = base + (long)j * QKVD + DIM + h * HD;
        float a = 0.f;
        #pragma unroll
        for (int dd = 0; dd < HD; dd++) a = fmaf(qsm[dd], kr[dd], a);
        a *= 0.125f;
        sc[j] = a;
        mloc = fmaxf(mloc, a);
    }
    #pragma unroll
    for (int o = 16; o > 0; o >>= 1) mloc = fmaxf(mloc, __shfl_xor_sync(0xffffffffu, mloc, o));
    if ((t & 31) == 0) red[t >> 5] = mloc;
    __syncthreads();
    float m = red[0];
    #pragma unroll
    for (int i = 1; i < 8; i++) m = fmaxf(m, red[i]);
    __syncthreads();
    float lsum = 0.f;
    for (int j = t; j < NTOK; j += 256) {
        float e = expf(sc[j] - m);
        sc[j] = e;
        lsum += e;
    }
    #pragma unroll
    for (int o = 16; o > 0; o >>= 1) lsum += __shfl_xor_sync(0xffffffffu, lsum, o);
    if ((t & 31) == 0) red[t >> 5] = lsum;
    __syncthreads();
    float tot = 0.f;
    #pragma unroll
    for (int i = 0; i < 8; i++) tot += red[i];
    float inv = 1.0f / tot;
    int g = t >> 6, dd = t & 63;
    float o = 0.f;
    for (int j = g; j < NTOK; j += 4)
        o = fmaf(sc[j], base[(long)j * QKVD + 2 * DIM + h * HD + dd], o);
    part[g * HD + dd] = o;
    __syncthreads();
    if (g == 0) {
        float r = (part[dd] + part[HD + dd] + part[2 * HD + dd] + part[3 * HD + dd]) * inv;
        att[(long)b * NTOK * DIM + h * HD + dd] = r;
    }
}

// ---------------- launcher ----------------
extern "C" void kernel_launch(void* const* d_in, const int* in_sizes, int n_in,
                              void* d_out, int out_size) {
    const float* x        = (const float*)d_in[0];
    const float* norm1_w  = (const float*)d_in[1];
    const float* norm1_b  = (const float*)d_in[2];
    const float* norm2_w  = (const float*)d_in[3];
    const float* norm2_b  = (const float*)d_in[4];
    const float* norm3_w  = (const float*)d_in[5];
    const float* norm3_b  = (const float*)d_in[6];
    const float* t_qkv_w  = (const float*)d_in[7];
    const float* t_qkv_b  = (const float*)d_in[8];
    const float* t_prj_w  = (const float*)d_in[9];
    const float* t_prj_b  = (const float*)d_in[10];
    const float* s_qkv_w  = (const float*)d_in[11];
    const float* s_qkv_b  = (const float*)d_in[12];
    const float* s_prj_w  = (const float*)d_in[13];
    const float* s_prj_b  = (const float*)d_in[14];
    const float* mlp_w1   = (const float*)d_in[15];
    const float* mlp_b1   = (const float*)d_in[16];
    const float* mlp_w2   = (const float*)d_in[17];
    const float* mlp_b2   = (const float*)d_in[18];
    float* out = (float*)d_out;

    float *ln, *qkvb, *attb, *h1;
    cudaGetSymbolAddress((void**)&ln,   g_ln);
    cudaGetSymbolAddress((void**)&qkvb, g_qkv);
    cudaGetSymbolAddress((void**)&attb, g_att);
    cudaGetSymbolAddress((void**)&h1,   g_h1);

    cudaFuncSetAttribute(space_attn_kernel,
                         cudaFuncAttributeMaxDynamicSharedMemorySize, SP_SMEM_BYTES);

    const int M = ROWS;
    dim3 gQKV (QKVD / Bb_N, (M + Bb_M - 1) / Bb_M);
    dim3 gPROJ(DIM  / Bb_N, (M + Bb_M - 1) / Bb_M);
    dim3 gMLP1(MLPD / Bb_N, (M + Bb_M - 1) / Bb_M);

    // ---- time attention branch ----
    ln_kernel<<<M, 256>>>(x, norm3_w, norm3_b, ln);
    gemm_kernel<<<gQKV, 256>>>(ln, t_qkv_w, t_qkv_b, nullptr, qkvb, M, QKVD, DIM, 0);
    time_attn_kernel<<<BB * NH * NS, 256>>>(qkvb, attb);
    cls_attn_kernel<<<BB * NH, 256>>>(qkvb, attb);
    gemm_kernel<<<gPROJ, 256>>>(attb, t_prj_w, t_prj_b, x, out, M, DIM, DIM, 0);

    // ---- space attention branch ----
    ln_kernel<<<M, 256>>>(out, norm1_w, norm1_b, ln);
    gemm_kernel<<<gQKV, 256>>>(ln, s_qkv_w, s_qkv_b, nullptr, qkvb, M, QKVD, DIM, 0);
    space_attn_kernel<<<BB * NH * NF, 256, SP_SMEM_BYTES>>>(qkvb, attb);
    cls_attn_kernel<<<BB * NH, 256>>>(qkvb, attb);
    gemm_kernel<<<gPROJ, 256>>>(attb, s_prj_w, s_prj_b, out, out, M, DIM, DIM, 0);

    // ---- MLP ----
    ln_kernel<<<M, 256>>>(out, norm2_w, norm2_b, ln);
    gemm_kernel<<<gMLP1, 256>>>(ln, mlp_w1, mlp_b1, nullptr, h1, M, MLPD, DIM, 1);
    gemm_kernel<<<gPROJ, 256>>>(h1, mlp_w2, mlp_b2, out, out, M, DIM, MLPD, 0);
}

// round 2
// speedup vs baseline: 2.1993x; 2.1993x over previous
#include <cuda_runtime.h>
#include <math.h>

// ---------------- problem constants ----------------
#define BB     16
#define NTOK   1569
#define DIM    768
#define NH     12
#define HD     64
#define NF     8
#define NS     196          // (NTOK-1)/NF
#define ROWS   (BB * NTOK)  // 25104
#define QKVD   (3 * DIM)    // 2304
#define MLPD   (4 * DIM)    // 3072

// ---------------- scratch (device globals; no runtime alloc) ----------------
__device__ float g_ln [ (long)ROWS * DIM  ];
__device__ float g_qkv[ (long)ROWS * QKVD ];
__device__ float g_att[ (long)ROWS * DIM  ];
__device__ float g_h1 [ (long)ROWS * MLPD ];

// ---------------- helpers ----------------
__device__ __forceinline__ float gelu_tanh(float x) {
    float x3 = x * x * x;
    float t  = tanhf(0.7978845608028654f * (x + 0.044715f * x3));
    return 0.5f * x * (1.0f + t);
}

__device__ __forceinline__ float tf32r(float x) {
    asm("cvt.rna.tf32.f32 %0, %0;" : "+f"(x));
    return x;
}

// ---------------- TF32 tensor-core GEMM ----------------
// C[M,N] = A[M,K] @ W[K,N] + bias (+gelu) (+res)
// 128x128x16 block tile, 256 threads, warp grid 2(M)x4(N), warp tile 64x32.
// mma.sync.aligned.m16n8k8.row.col.f32.tf32.tf32.f32
#define TM 128
#define TN 128
#define TK 16
#define SPAD 8

__global__ __launch_bounds__(256)
void gemm_tf32_kernel(const float* __restrict__ A, const float* __restrict__ W,
                      const float* __restrict__ bias, const float* __restrict__ res,
                      float* __restrict__ C, int M, int N, int K, int act) {
    __shared__ float As[TK][TM + SPAD];
    __shared__ float Bs[TK][TN + SPAD];

    int bx = blockIdx.x, by = blockIdx.y;
    int tid = threadIdx.x;
    int wid = tid >> 5, lane = tid & 31;
    int wm = wid >> 2;          // 0..1  (M dir, 64 rows)
    int wn = wid & 3;           // 0..3  (N dir, 32 cols)
    int grp = lane >> 2;        // 0..7
    int tig = lane & 3;         // 0..3

    float acc[4][4][4];
    #pragma unroll
    for (int i = 0; i < 4; i++)
        #pragma unroll
        for (int j = 0; j < 4; j++)
            #pragma unroll
            for (int r = 0; r < 4; r++) acc[i][j][r] = 0.f;

    const float* Ab = A + (long)by * TM * K;
    const float* Wb = W + bx * TN;

    // A tile: 128 rows x 16 cols = 512 float4; f4id = tid + p*256
    // B tile: 16 rows x 128 cols = 512 float4
    int aRow0 = tid >> 2;            // 0..63  (p adds 64)
    int aColq = (tid & 3) * 4;       // 0,4,8,12
    int bRow0 = tid >> 5;            // 0..7   (p adds 8)
    int bCol  = (tid & 31) * 4;      // 0..124

    for (int k0 = 0; k0 < K; k0 += TK) {
        // load A (transposed into k-major smem), cvt tf32
        #pragma unroll
        for (int p = 0; p < 2; p++) {
            int r = aRow0 + p * 64;
            long grow = (long)by * TM + r;
            float4 av = (grow < M) ? *(const float4*)(Ab + (long)r * K + k0 + aColq)
                                   : make_float4(0.f, 0.f, 0.f, 0.f);
            As[aColq + 0][r] = tf32r(av.x);
            As[aColq + 1][r] = tf32r(av.y);
            As[aColq + 2][r] = tf32r(av.z);
            As[aColq + 3][r] = tf32r(av.w);
        }
        // load B (k-major), cvt tf32
        #pragma unroll
        for (int p = 0; p < 2; p++) {
            int r = bRow0 + p * 8;
            float4 wv = *(const float4*)(Wb + (long)(k0 + r) * N + bCol);
            Bs[r][bCol + 0] = tf32r(wv.x);
            Bs[r][bCol + 1] = tf32r(wv.y);
            Bs[r][bCol + 2] = tf32r(wv.z);
            Bs[r][bCol + 3] = tf32r(wv.w);
        }
        __syncthreads();

        #pragma unroll
        for (int ks = 0; ks < TK; ks += 8) {
            unsigned au[4][4];
            #pragma unroll
            for (int mi = 0; mi < 4; mi++) {
                int m = wm * 64 + mi * 16;
                au[mi][0] = __float_as_uint(As[ks + tig    ][m + grp    ]);
                au[mi][1] = __float_as_uint(As[ks + tig    ][m + grp + 8]);
                au[mi][2] = __float_as_uint(As[ks + tig + 4][m + grp    ]);
                au[mi][3] = __float_as_uint(As[ks + tig + 4][m + grp + 8]);
            }
            unsigned bu[4][2];
            #pragma unroll
            for (int nj = 0; nj < 4; nj++) {
                int n = wn * 32 + nj * 8;
                bu[nj][0] = __float_as_uint(Bs[ks + tig    ][n + grp]);
                bu[nj][1] = __float_as_uint(Bs[ks + tig + 4][n + grp]);
            }
            #pragma unroll
            for (int mi = 0; mi < 4; mi++)
                #pragma unroll
                for (int nj = 0; nj < 4; nj++) {
                    asm volatile(
                        "mma.sync.aligned.m16n8k8.row.col.f32.tf32.tf32.f32 "
                        "{%0,%1,%2,%3}, {%4,%5,%6,%7}, {%8,%9}, {%0,%1,%2,%3};\n"
                        : "+f"(acc[mi][nj][0]), "+f"(acc[mi][nj][1]),
                          "+f"(acc[mi][nj][2]), "+f"(acc[mi][nj][3])
                        : "r"(au[mi][0]), "r"(au[mi][1]), "r"(au[mi][2]), "r"(au[mi][3]),
                          "r"(bu[nj][0]), "r"(bu[nj][1]));
                }
        }
        __syncthreads();
    }

    // epilogue
    #pragma unroll
    for (int mi = 0; mi < 4; mi++) {
        #pragma unroll
        for (int half = 0; half < 2; half++) {
            long row = (long)by * TM + wm * 64 + mi * 16 + grp + half * 8;
            if (row >= M) continue;
            float* Crow = C + row * N;
            const float* Rrow = res ? res + row * N : nullptr;
            #pragma unroll
            for (int nj = 0; nj < 4; nj++) {
                int col = bx * TN + wn * 32 + nj * 8 + tig * 2;
                float v0 = acc[mi][nj][half * 2 + 0] + bias[col];
                float v1 = acc[mi][nj][half * 2 + 1] + bias[col + 1];
                if (act) { v0 = gelu_tanh(v0); v1 = gelu_tanh(v1); }
                if (Rrow) { v0 += Rrow[col]; v1 += Rrow[col + 1]; }
                Crow[col]     = v0;
                Crow[col + 1] = v1;
            }
        }
    }
}

// ---------------- LayerNorm over last dim (768), 256 thr, 3 elems/thr ----------------
__global__ void ln_kernel(const float* __restrict__ x, const float* __restrict__ w,
                          const float* __restrict__ b, float* __restrict__ out) {
    long row = blockIdx.x;
    const float* xr = x + row * DIM;
    float* orow = out + row * DIM;
    int t = threadIdx.x;
    float v0 = xr[t], v1 = xr[t + 256], v2 = xr[t + 512];
    float s  = v0 + v1 + v2;
    float s2 = v0 * v0 + v1 * v1 + v2 * v2;
    #pragma unroll
    for (int o = 16; o > 0; o >>= 1) {
        s  += __shfl_xor_sync(0xffffffffu, s,  o);
        s2 += __shfl_xor_sync(0xffffffffu, s2, o);
    }
    __shared__ float sh[64];
    int wid = t >> 5, lane = t & 31;
    if (lane == 0) { sh[wid] = s; sh[32 + wid] = s2; }
    __syncthreads();
    float ts = 0.f, ts2 = 0.f;
    #pragma unroll
    for (int i = 0; i < 8; i++) { ts += sh[i]; ts2 += sh[32 + i]; }
    float mean = ts * (1.0f / DIM);
    float var  = ts2 * (1.0f / DIM) - mean * mean;
    float inv  = rsqrtf(var + 1e-6f);
    orow[t]       = (v0 - mean) * inv * w[t]       + b[t];
    orow[t + 256] = (v1 - mean) * inv * w[t + 256] + b[t + 256];
    orow[t + 512] = (v2 - mean) * inv * w[t + 512] + b[t + 512];
}

// ---------------- time attention ----------------
__global__ __launch_bounds__(256)
void time_attn_kernel(const float* __restrict__ qkv, float* __restrict__ att) {
    int blk = blockIdx.x;
    int n = blk % NS;
    int h = (blk / NS) % NH;
    int b = blk / (NS * NH);
    __shared__ float ks[9][HD], vs[9][HD];
    const float* base = qkv + (long)b * NTOK * QKVD;
    int qoff = h * HD;
    int t = threadIdx.x;
    for (int i = t; i < 9 * HD; i += 256) {
        int j = i / HD, dd = i % HD;
        int tok = (j == 0) ? 0 : 1 + (j - 1) * NS + n;
        const float* row = base + (long)tok * QKVD;
        ks[j][dd] = row[DIM + qoff + dd];
        vs[j][dd] = row[2 * DIM + qoff + dd];
    }
    __syncthreads();
    int f = t >> 5, lane = t & 31;
    int qtok = 1 + f * NS + n;
    const float* qrow = base + (long)qtok * QKVD + qoff;
    float q0 = qrow[lane], q1 = qrow[lane + 32];
    float sc[9];
    #pragma unroll
    for (int j = 0; j < 9; j++) {
        float p = q0 * ks[j][lane] + q1 * ks[j][lane + 32];
        #pragma unroll
        for (int o = 16; o > 0; o >>= 1) p += __shfl_xor_sync(0xffffffffu, p, o);
        sc[j] = p * 0.125f;
    }
    float m = sc[0];
    #pragma unroll
    for (int j = 1; j < 9; j++) m = fmaxf(m, sc[j]);
    float l = 0.f;
    #pragma unroll
    for (int j = 0; j < 9; j++) { sc[j] = expf(sc[j] - m); l += sc[j]; }
    float inv = 1.0f / l;
    float o0 = 0.f, o1 = 0.f;
    #pragma unroll
    for (int j = 0; j < 9; j++) {
        o0 = fmaf(sc[j], vs[j][lane], o0);
        o1 = fmaf(sc[j], vs[j][lane + 32], o1);
    }
    float* orow = att + (long)b * NTOK * DIM + (long)qtok * DIM + h * HD;
    orow[lane]      = o0 * inv;
    orow[lane + 32] = o1 * inv;
}

// ---------------- space attention ----------------
#define SP_KV_PAD 65
#define SP_KS_OFF 0
#define SP_VS_OFF (197 * SP_KV_PAD)
#define SP_P_OFF  (2 * 197 * SP_KV_PAD)
#define SP_Q_OFF  (SP_P_OFF + 8 * 200)
#define SP_SMEM_FLOATS (SP_Q_OFF + 8 * 64)
#define SP_SMEM_BYTES (SP_SMEM_FLOATS * 4)

__global__ __launch_bounds__(256)
void space_attn_kernel(const float* __restrict__ qkv, float* __restrict__ att) {
    extern __shared__ float sm[];
    float* Ks = sm + SP_KS_OFF;
    float* Vs = sm + SP_VS_OFF;
    int blk = blockIdx.x;
    int f = blk % NF;
    int h = (blk / NF) % NH;
    int b = blk / (NF * NH);
    const float* base = qkv + (long)b * NTOK * QKVD;
    int qoff = h * HD;
    int t = threadIdx.x;
    for (int i = t; i < 197 * HD; i += 256) {
        int j = i / HD, dd = i % HD;
        int tok = (j == 0) ? 0 : 1 + f * NS + (j - 1);
        const float* row = base + (long)tok * QKVD;
        Ks[j * SP_KV_PAD + dd] = row[DIM + qoff + dd];
        Vs[j * SP_KV_PAD + dd] = row[2 * DIM + qoff + dd];
    }
    __syncthreads();
    int w = t >> 5, lane = t & 31;
    float* p  = sm + SP_P_OFF + w * 200;
    float* qs = sm + SP_Q_OFF + w * 64;
    for (int n = w; n < NS; n += 8) {
        int qtok = 1 + f * NS + n;
        const float* qrow = base + (long)qtok * QKVD + qoff;
        qs[lane]      = qrow[lane];
        qs[lane + 32] = qrow[lane + 32];
        __syncwarp();
        float s[7];
        float mloc = -1e30f;
        #pragma unroll
        for (int kk = 0; kk < 7; kk++) {
            int j = lane + kk * 32;
            float a = -1e30f;
            if (j < 197) {
                a = 0.f;
                const float* kr = Ks + j * SP_KV_PAD;
                #pragma unroll
                for (int dd = 0; dd < HD; dd++) a = fmaf(qs[dd], kr[dd], a);
                a *= 0.125f;
            }
            s[kk] = a;
            mloc = fmaxf(mloc, a);
        }
        #pragma unroll
        for (int o = 16; o > 0; o >>= 1) mloc = fmaxf(mloc, __shfl_xor_sync(0xffffffffu, mloc, o));
        float lsum = 0.f;
        #pragma unroll
        for (int kk = 0; kk < 7; kk++) {
            int j = lane + kk * 32;
            if (j < 197) { s[kk] = expf(s[kk] - mloc); lsum += s[kk]; }
        }
        #pragma unroll
        for (int o = 16; o > 0; o >>= 1) lsum += __shfl_xor_sync(0xffffffffu, lsum, o);
        float inv = 1.0f / lsum;
        #pragma unroll
        for (int kk = 0; kk < 7; kk++) {
            int j = lane + kk * 32;
            if (j < 197) p[j] = s[kk] * inv;
        }
        __syncwarp();
        float o0 = 0.f, o1 = 0.f;
        for (int j = 0; j < 197; j++) {
            float pj = p[j];
            o0 = fmaf(pj, Vs[j * SP_KV_PAD + lane], o0);
            o1 = fmaf(pj, Vs[j * SP_KV_PAD + lane + 32], o1);
        }
        float* orow = att + (long)b * NTOK * DIM + (long)qtok * DIM + h * HD;
        orow[lane]      = o0;
        orow[lane + 32] = o1;
        __syncwarp();
    }
}

// ---------------- cls attention ----------------
__global__ __launch_bounds__(256)
void cls_attn_kernel(const float* __restrict__ qkv, float* __restrict__ att) {
    int h = blockIdx.x % NH;
    int b = blockIdx.x / NH;
    const float* base = qkv + (long)b * NTOK * QKVD;
    __shared__ float qsm[HD];
    __shared__ float sc[NTOK];
    __shared__ float red[32];
    __shared__ float part[4 * HD];
    int t = threadIdx.x;
    if (t < HD) qsm[t] = base[h * HD + t];
    __syncthreads();
    float mloc = -1e30f;
    for (int j = t; j < NTOK; j += 256) {
        const float* kr = base + (long)j * QKVD + DIM + h * HD;
        float a = 0.f;
        #pragma unroll
        for (int dd = 0; dd < HD; dd++) a = fmaf(qsm[dd], kr[dd], a);
        a *= 0.125f;
        sc[j] = a;
        mloc = fmaxf(mloc, a);
    }
    #pragma unroll
    for (int o = 16; o > 0; o >>= 1) mloc = fmaxf(mloc, __shfl_xor_sync(0xffffffffu, mloc, o));
    if ((t & 31) == 0) red[t >> 5] = mloc;
    __syncthreads();
    float m = red[0];
    #pragma unroll
    for (int i = 1; i < 8; i++) m = fmaxf(m, red[i]);
    __syncthreads();
    float lsum = 0.f;
    for (int j = t; j < NTOK; j += 256) {
        float e = expf(sc[j] - m);
        sc[j] = e;
        lsum += e;
    }
    #pragma unroll
    for (int o = 16; o > 0; o >>= 1) lsum += __shfl_xor_sync(0xffffffffu, lsum, o);
    if ((t & 31) == 0) red[t >> 5] = lsum;
    __syncthreads();
    float tot = 0.f;
    #pragma unroll
    for (int i = 0; i < 8; i++) tot += red[i];
    float inv = 1.0f / tot;
    int g = t >> 6, dd = t & 63;
    float o = 0.f;
    for (int j = g; j < NTOK; j += 4)
        o = fmaf(sc[j], base[(long)j * QKVD + 2 * DIM + h * HD + dd], o);
    part[g * HD + dd] = o;
    __syncthreads();
    if (g == 0) {
        float r = (part[dd] + part[HD + dd] + part[2 * HD + dd] + part[3 * HD + dd]) * inv;
        att[(long)b * NTOK * DIM + h * HD + dd] = r;
    }
}

// ---------------- launcher ----------------
extern "C" void kernel_launch(void* const* d_in, const int* in_sizes, int n_in,
                              void* d_out, int out_size) {
    const float* x        = (const float*)d_in[0];
    const float* norm1_w  = (const float*)d_in[1];
    const float* norm1_b  = (const float*)d_in[2];
    const float* norm2_w  = (const float*)d_in[3];
    const float* norm2_b  = (const float*)d_in[4];
    const float* norm3_w  = (const float*)d_in[5];
    const float* norm3_b  = (const float*)d_in[6];
    const float* t_qkv_w  = (const float*)d_in[7];
    const float* t_qkv_b  = (const float*)d_in[8];
    const float* t_prj_w  = (const float*)d_in[9];
    const float* t_prj_b  = (const float*)d_in[10];
    const float* s_qkv_w  = (const float*)d_in[11];
    const float* s_qkv_b  = (const float*)d_in[12];
    const float* s_prj_w  = (const float*)d_in[13];
    const float* s_prj_b  = (const float*)d_in[14];
    const float* mlp_w1   = (const float*)d_in[15];
    const float* mlp_b1   = (const float*)d_in[16];
    const float* mlp_w2   = (const float*)d_in[17];
    const float* mlp_b2   = (const float*)d_in[18];
    float* out = (float*)d_out;

    float *ln, *qkvb, *attb, *h1;
    cudaGetSymbolAddress((void**)&ln,   g_ln);
    cudaGetSymbolAddress((void**)&qkvb, g_qkv);
    cudaGetSymbolAddress((void**)&attb, g_att);
    cudaGetSymbolAddress((void**)&h1,   g_h1);

    cudaFuncSetAttribute(space_attn_kernel,
                         cudaFuncAttributeMaxDynamicSharedMemorySize, SP_SMEM_BYTES);

    const int M = ROWS;
    dim3 gQKV (QKVD / TN, (M + TM - 1) / TM);
    dim3 gPROJ(DIM  / TN, (M + TM - 1) / TM);
    dim3 gMLP1(MLPD / TN, (M + TM - 1) / TM);

    // ---- time attention branch ----
    ln_kernel<<<M, 256>>>(x, norm3_w, norm3_b, ln);
    gemm_tf32_kernel<<<gQKV, 256>>>(ln, t_qkv_w, t_qkv_b, nullptr, qkvb, M, QKVD, DIM, 0);
    time_attn_kernel<<<BB * NH * NS, 256>>>(qkvb, attb);
    cls_attn_kernel<<<BB * NH, 256>>>(qkvb, attb);
    gemm_tf32_kernel<<<gPROJ, 256>>>(attb, t_prj_w, t_prj_b, x, out, M, DIM, DIM, 0);

    // ---- space attention branch ----
    ln_kernel<<<M, 256>>>(out, norm1_w, norm1_b, ln);
    gemm_tf32_kernel<<<gQKV, 256>>>(ln, s_qkv_w, s_qkv_b, nullptr, qkvb, M, QKVD, DIM, 0);
    space_attn_kernel<<<BB * NH * NF, 256, SP_SMEM_BYTES>>>(qkvb, attb);
    cls_attn_kernel<<<BB * NH, 256>>>(qkvb, attb);
    gemm_tf32_kernel<<<gPROJ, 256>>>(attb, s_prj_w, s_prj_b, out, out, M, DIM, DIM, 0);

    // ---- MLP ----
    ln_kernel<<<M, 256>>>(out, norm2_w, norm2_b, ln);
    gemm_tf32_kernel<<<gMLP1, 256>>>(ln, mlp_w1, mlp_b1, nullptr, h1, M, MLPD, DIM, 1);
    gemm_tf32_kernel<<<gPROJ, 256>>>(h1, mlp_w2, mlp_b2, out, out, M, DIM, MLPD, 0);
}

// round 5
// speedup vs baseline: 2.8335x; 1.2884x over previous
#include <cuda_runtime.h>
#include <math.h>

// ---------------- problem constants ----------------
#define BB     16
#define NTOK   1569
#define DIM    768
#define NH     12
#define HD     64
#define NF     8
#define NS     196          // (NTOK-1)/NF
#define ROWS   (BB * NTOK)  // 25104
#define QKVD   (3 * DIM)    // 2304
#define MLPD   (4 * DIM)    // 3072
#define CSPLIT 8

// ---------------- scratch (device globals; no runtime alloc) ----------------
__device__ float g_ln  [ (long)ROWS * DIM  ];
__device__ float g_qkv [ (long)ROWS * QKVD ];
__device__ float g_att [ (long)ROWS * DIM  ];
__device__ float g_h1  [ (long)ROWS * MLPD ];
__device__ float g_clsp[ (long)BB * NH * CSPLIT * (HD + 2) ];

// ---------------- helpers ----------------
__device__ __forceinline__ float gelu_tanh(float x) {
    float x3 = x * x * x;
    float t  = tanhf(0.7978845608028654f * (x + 0.044715f * x3));
    return 0.5f * x * (1.0f + t);
}

__device__ __forceinline__ void cp_async16(void* smem_ptr, const void* gmem_ptr, int src_bytes) {
    unsigned saddr = (unsigned)__cvta_generic_to_shared(smem_ptr);
    asm volatile("cp.async.cg.shared.global [%0], [%1], 16, %2;\n"
                 :: "r"(saddr), "l"(gmem_ptr), "r"(src_bytes));
}
__device__ __forceinline__ void cp_commit() {
    asm volatile("cp.async.commit_group;\n");
}
template <int N>
__device__ __forceinline__ void cp_wait() {
    asm volatile("cp.async.wait_group %0;\n" :: "n"(N));
}

// ---------------- TF32 tensor-core GEMM, 2-stage cp.async pipeline ----------------
// C[M,N] = A[M,K] @ W[K,N] + bias (+gelu) (+res)
// 128x128x16 block tile, 256 threads, warp grid 2(M)x4(N), warp tile 64x32.
#define TM 128
#define TN 128
#define TK 16
#define APAD 4
#define BPAD 8

__global__ __launch_bounds__(256, 2)
void gemm_tf32_kernel(const float* __restrict__ A, const float* __restrict__ W,
                      const float* __restrict__ bias, const float* __restrict__ res,
                      float* __restrict__ C, int M, int N, int K, int act) {
    __shared__ float As[2][TM][TK + APAD];   // m-major
    __shared__ float Bs[2][TK][TN + BPAD];   // k-major

    int bx = blockIdx.x, by = blockIdx.y;
    int tid = threadIdx.x;
    int wid = tid >> 5, lane = tid & 31;
    int wm = wid >> 2;          // 0..1  (M dir, 64 rows)
    int wn = wid & 3;           // 0..3  (N dir, 32 cols)
    int grp = lane >> 2;        // 0..7
    int tig = lane & 3;         // 0..3

    float acc[4][4][4];
    #pragma unroll
    for (int i = 0; i < 4; i++)
        #pragma unroll
        for (int j = 0; j < 4; j++)
            #pragma unroll
            for (int r = 0; r < 4; r++) acc[i][j][r] = 0.f;

    const float* Ab = A + (long)by * TM * K;
    const float* Wb = W + bx * TN;

    int aRow0 = tid >> 2;           // 0..63 (p adds 64)
    int aColq = (tid & 3) * 4;      // 0,4,8,12
    // B: chunk c = tid + p*256; row=c>>5 (0..15), colq=(c&31)*4

    int KT = K / TK;

    // ---- prologue: stage 0 ----
    {
        #pragma unroll
        for (int p = 0; p < 2; p++) {
            int r = aRow0 + p * 64;
            long grow = (long)by * TM + r;
            long srcrow = grow < M ? (long)r : 0;
            cp_async16(&As[0][r][aColq], Ab + srcrow * K + aColq, grow < M ? 16 : 0);
        }
        #pragma unroll
        for (int p = 0; p < 2; p++) {
            int c = tid + p * 256;
            int r = c >> 5, cq = (c & 31) * 4;
            cp_async16(&Bs[0][r][cq], Wb + (long)r * N + cq, 16);
        }
        cp_commit();
    }

    for (int kt = 0; kt < KT; kt++) {
        int s = kt & 1;
        if (kt + 1 < KT) {
            int k0 = (kt + 1) * TK;
            #pragma unroll
            for (int p = 0; p < 2; p++) {
                int r = aRow0 + p * 64;
                long grow = (long)by * TM + r;
                long srcrow = grow < M ? (long)r : 0;
                cp_async16(&As[s ^ 1][r][aColq], Ab + srcrow * K + k0 + aColq,
                           grow < M ? 16 : 0);
            }
            #pragma unroll
            for (int p = 0; p < 2; p++) {
                int c = tid + p * 256;
                int r = c >> 5, cq = (c & 31) * 4;
                cp_async16(&Bs[s ^ 1][r][cq], Wb + (long)(k0 + r) * N + cq, 16);
            }
            cp_commit();
            cp_wait<1>();
        } else {
            cp_wait<0>();
        }
        __syncthreads();

        #pragma unroll
        for (int ks = 0; ks < TK; ks += 8) {
            unsigned au[4][4];
            #pragma unroll
            for (int mi = 0; mi < 4; mi++) {
                int m = wm * 64 + mi * 16;
                au[mi][0] = __float_as_uint(As[s][m + grp    ][ks + tig    ]);
                au[mi][1] = __float_as_uint(As[s][m + grp + 8][ks + tig    ]);
                au[mi][2] = __float_as_uint(As[s][m + grp    ][ks + tig + 4]);
                au[mi][3] = __float_as_uint(As[s][m + grp + 8][ks + tig + 4]);
            }
            unsigned bu[4][2];
            #pragma unroll
            for (int nj = 0; nj < 4; nj++) {
                int n = wn * 32 + nj * 8;
                bu[nj][0] = __float_as_uint(Bs[s][ks + tig    ][n + grp]);
                bu[nj][1] = __float_as_uint(Bs[s][ks + tig + 4][n + grp]);
            }
            #pragma unroll
            for (int mi = 0; mi < 4; mi++)
                #pragma unroll
                for (int nj = 0; nj < 4; nj++) {
                    asm volatile(
                        "mma.sync.aligned.m16n8k8.row.col.f32.tf32.tf32.f32 "
                        "{%0,%1,%2,%3}, {%4,%5,%6,%7}, {%8,%9}, {%0,%1,%2,%3};\n"
                        : "+f"(acc[mi][nj][0]), "+f"(acc[mi][nj][1]),
                          "+f"(acc[mi][nj][2]), "+f"(acc[mi][nj][3])
                        : "r"(au[mi][0]), "r"(au[mi][1]), "r"(au[mi][2]), "r"(au[mi][3]),
                          "r"(bu[nj][0]), "r"(bu[nj][1]));
                }
        }
        __syncthreads();
    }

    // epilogue
    #pragma unroll
    for (int mi = 0; mi < 4; mi++) {
        #pragma unroll
        for (int half = 0; half < 2; half++) {
            long row = (long)by * TM + wm * 64 + mi * 16 + grp + half * 8;
            if (row >= M) continue;
            float* Crow = C + row * N;
            const float* Rrow = res ? res + row * N : nullptr;
            #pragma unroll
            for (int nj = 0; nj < 4; nj++) {
                int col = bx * TN + wn * 32 + nj * 8 + tig * 2;
                float v0 = acc[mi][nj][half * 2 + 0] + bias[col];
                float v1 = acc[mi][nj][half * 2 + 1] + bias[col + 1];
                if (act) { v0 = gelu_tanh(v0); v1 = gelu_tanh(v1); }
                if (Rrow) { v0 += Rrow[col]; v1 += Rrow[col + 1]; }
                Crow[col]     = v0;
                Crow[col + 1] = v1;
            }
        }
    }
}

// ---------------- LayerNorm over last dim (768), 256 thr, 3 elems/thr ----------------
__global__ void ln_kernel(const float* __restrict__ x, const float* __restrict__ w,
                          const float* __restrict__ b, float* __restrict__ out) {
    long row = blockIdx.x;
    const float* xr = x + row * DIM;
    float* orow = out + row * DIM;
    int t = threadIdx.x;
    float v0 = xr[t], v1 = xr[t + 256], v2 = xr[t + 512];
    float s  = v0 + v1 + v2;
    float s2 = v0 * v0 + v1 * v1 + v2 * v2;
    #pragma unroll
    for (int o = 16; o > 0; o >>= 1) {
        s  += __shfl_xor_sync(0xffffffffu, s,  o);
        s2 += __shfl_xor_sync(0xffffffffu, s2, o);
    }
    __shared__ float sh[64];
    int wid = t >> 5, lane = t & 31;
    if (lane == 0) { sh[wid] = s; sh[32 + wid] = s2; }
    __syncthreads();
    float ts = 0.f, ts2 = 0.f;
    #pragma unroll
    for (int i = 0; i < 8; i++) { ts += sh[i]; ts2 += sh[32 + i]; }
    float mean = ts * (1.0f / DIM);
    float var  = ts2 * (1.0f / DIM) - mean * mean;
    float inv  = rsqrtf(var + 1e-6f);
    orow[t]       = (v0 - mean) * inv * w[t]       + b[t];
    orow[t + 256] = (v1 - mean) * inv * w[t + 256] + b[t + 256];
    orow[t + 512] = (v2 - mean) * inv * w[t + 512] + b[t + 512];
}

// ---------------- time attention ----------------
__global__ __launch_bounds__(256)
void time_attn_kernel(const float* __restrict__ qkv, float* __restrict__ att) {
    int blk = blockIdx.x;
    int n = blk % NS;
    int h = (blk / NS) % NH;
    int b = blk / (NS * NH);
    __shared__ float ks[9][HD], vs[9][HD];
    const float* base = qkv + (long)b * NTOK * QKVD;
    int qoff = h * HD;
    int t = threadIdx.x;
    for (int i = t; i < 9 * HD; i += 256) {
        int j = i / HD, dd = i % HD;
        int tok = (j == 0) ? 0 : 1 + (j - 1) * NS + n;
        const float* row = base + (long)tok * QKVD;
        ks[j][dd] = row[DIM + qoff + dd];
        vs[j][dd] = row[2 * DIM + qoff + dd];
    }
    __syncthreads();
    int f = t >> 5, lane = t & 31;
    int qtok = 1 + f * NS + n;
    const float* qrow = base + (long)qtok * QKVD + qoff;
    float q0 = qrow[lane], q1 = qrow[lane + 32];
    float sc[9];
    #pragma unroll
    for (int j = 0; j < 9; j++) {
        float p = q0 * ks[j][lane] + q1 * ks[j][lane + 32];
        #pragma unroll
        for (int o = 16; o > 0; o >>= 1) p += __shfl_xor_sync(0xffffffffu, p, o);
        sc[j] = p * 0.125f;
    }
    float m = sc[0];
    #pragma unroll
    for (int j = 1; j < 9; j++) m = fmaxf(m, sc[j]);
    float l = 0.f;
    #pragma unroll
    for (int j = 0; j < 9; j++) { sc[j] = expf(sc[j] - m); l += sc[j]; }
    float inv = 1.0f / l;
    float o0 = 0.f, o1 = 0.f;
    #pragma unroll
    for (int j = 0; j < 9; j++) {
        o0 = fmaf(sc[j], vs[j][lane], o0);
        o1 = fmaf(sc[j], vs[j][lane + 32], o1);
    }
    float* orow = att + (long)b * NTOK * DIM + (long)qtok * DIM + h * HD;
    orow[lane]      = o0 * inv;
    orow[lane + 32] = o1 * inv;
}

// ---------------- space attention ----------------
#define SP_KV_PAD 65
#define SP_KS_OFF 0
#define SP_VS_OFF (197 * SP_KV_PAD)
#define SP_P_OFF  (2 * 197 * SP_KV_PAD)
#define SP_Q_OFF  (SP_P_OFF + 8 * 200)
#define SP_SMEM_FLOATS (SP_Q_OFF + 8 * 64)
#define SP_SMEM_BYTES (SP_SMEM_FLOATS * 4)

__global__ __launch_bounds__(256)
void space_attn_kernel(const float* __restrict__ qkv, float* __restrict__ att) {
    extern __shared__ float sm[];
    float* Ks = sm + SP_KS_OFF;
    float* Vs = sm + SP_VS_OFF;
    int blk = blockIdx.x;
    int f = blk % NF;
    int h = (blk / NF) % NH;
    int b = blk / (NF * NH);
    const float* base = qkv + (long)b * NTOK * QKVD;
    int qoff = h * HD;
    int t = threadIdx.x;
    for (int i = t; i < 197 * HD; i += 256) {
        int j = i / HD, dd = i % HD;
        int tok = (j == 0) ? 0 : 1 + f * NS + (j - 1);
        const float* row = base + (long)tok * QKVD;
        Ks[j * SP_KV_PAD + dd] = row[DIM + qoff + dd];
        Vs[j * SP_KV_PAD + dd] = row[2 * DIM + qoff + dd];
    }
    __syncthreads();
    int w = t >> 5, lane = t & 31;
    float* p  = sm + SP_P_OFF + w * 200;
    float* qs = sm + SP_Q_OFF + w * 64;
    for (int n = w; n < NS; n += 8) {
        int qtok = 1 + f * NS + n;
        const float* qrow = base + (long)qtok * QKVD + qoff;
        qs[lane]      = qrow[lane];
        qs[lane + 32] = qrow[lane + 32];
        __syncwarp();
        float s[7];
        float mloc = -1e30f;
        #pragma unroll
        for (int kk = 0; kk < 7; kk++) {
            int j = lane + kk * 32;
            float a = -1e30f;
            if (j < 197) {
                a = 0.f;
                const float* kr = Ks + j * SP_KV_PAD;
                #pragma unroll
                for (int dd = 0; dd < HD; dd++) a = fmaf(qs[dd], kr[dd], a);
                a *= 0.125f;
            }
            s[kk] = a;
            mloc = fmaxf(mloc, a);
        }
        #pragma unroll
        for (int o = 16; o > 0; o >>= 1) mloc = fmaxf(mloc, __shfl_xor_sync(0xffffffffu, mloc, o));
        float lsum = 0.f;
        #pragma unroll
        for (int kk = 0; kk < 7; kk++) {
            int j = lane + kk * 32;
            if (j < 197) { s[kk] = expf(s[kk] - mloc); lsum += s[kk]; }
        }
        #pragma unroll
        for (int o = 16; o > 0; o >>= 1) lsum += __shfl_xor_sync(0xffffffffu, lsum, o);
        float inv = 1.0f / lsum;
        #pragma unroll
        for (int kk = 0; kk < 7; kk++) {
            int j = lane + kk * 32;
            if (j < 197) p[j] = s[kk] * inv;
        }
        __syncwarp();
        float o0 = 0.f, o1 = 0.f;
        for (int j = 0; j < 197; j++) {
            float pj = p[j];
            o0 = fmaf(pj, Vs[j * SP_KV_PAD + lane], o0);
            o1 = fmaf(pj, Vs[j * SP_KV_PAD + lane + 32], o1);
        }
        float* orow = att + (long)b * NTOK * DIM + (long)qtok * DIM + h * HD;
        orow[lane]      = o0;
        orow[lane + 32] = o1;
        __syncwarp();
    }
}

// ---------------- cls attention: split-K flash partials ----------------
__global__ __launch_bounds__(256)
void cls_part_kernel(const float* __restrict__ qkv, float* __restrict__ part) {
    int blk = blockIdx.x;
    int c = blk % CSPLIT;
    int h = (blk / CSPLIT) % NH;
    int b = blk / (CSPLIT * NH);
    const float* base = qkv + (long)b * NTOK * QKVD;
    int lane = threadIdx.x & 31, w = threadIdx.x >> 5;
    float q0 = base[h * HD + lane], q1 = base[h * HD + lane + 32];
    int j0 = (c * NTOK) / CSPLIT, j1 = ((c + 1) * NTOK) / CSPLIT;
    float m = -1e30f, l = 0.f, o0 = 0.f, o1 = 0.f;
    for (int j = j0 + w; j < j1; j += 8) {
        const float* kr = base + (long)j * QKVD + DIM + h * HD;
        float p = q0 * kr[lane] + q1 * kr[lane + 32];
        #pragma unroll
        for (int o = 16; o > 0; o >>= 1) p += __shfl_xor_sync(0xffffffffu, p, o);
        p *= 0.125f;
        float nm = fmaxf(m, p);
        float scale = expf(m - nm);
        float e = expf(p - nm);
        const float* vr = base + (long)j * QKVD + 2 * DIM + h * HD;
        l  = l  * scale + e;
        o0 = o0 * scale + e * vr[lane];
        o1 = o1 * scale + e * vr[lane + 32];
        m = nm;
    }
    __shared__ float sO[8][64];
    __shared__ float sM[8], sL[8];
    if (lane == 0) { sM[w] = m; sL[w] = l; }
    sO[w][lane] = o0;
    sO[w][lane + 32] = o1;
    __syncthreads();
    if (threadIdx.x < 64) {
        int dd = threadIdx.x;
        float M = sM[0];
        #pragma unroll
        for (int i = 1; i < 8; i++) M = fmaxf(M, sM[i]);
        float L = 0.f, O = 0.f;
        #pragma unroll
        for (int i = 0; i < 8; i++) {
            float sc = expf(sM[i] - M);
            O += sO[i][dd] * sc;
            L += sL[i] * sc;
        }
        float* pp = part + ((long)(b * NH + h) * CSPLIT + c) * (HD + 2);
        pp[dd] = O;
        if (dd == 0) { pp[HD] = M; pp[HD + 1] = L; }
    }
}

__global__ void cls_reduce_kernel(const float* __restrict__ part, float* __restrict__ att) {
    int h = blockIdx.x % NH, b = blockIdx.x / NH;
    int dd = threadIdx.x;  // 64
    const float* pp = part + (long)(b * NH + h) * CSPLIT * (HD + 2);
    float M = -1e30f;
    #pragma unroll
    for (int c = 0; c < CSPLIT; c++) M = fmaxf(M, pp[c * (HD + 2) + HD]);
    float L = 0.f, O = 0.f;
    #pragma unroll
    for (int c = 0; c < CSPLIT; c++) {
        float sc = expf(pp[c * (HD + 2) + HD] - M);
        O += pp[c * (HD + 2) + dd] * sc;
        L += pp[c * (HD + 2) + HD + 1] * sc;
    }
    att[(long)b * NTOK * DIM + h * HD + dd] = O / L;
}

// ---------------- launcher ----------------
extern "C" void kernel_launch(void* const* d_in, const int* in_sizes, int n_in,
                              void* d_out, int out_size) {
    const float* x        = (const float*)d_in[0];
    const float* norm1_w  = (const float*)d_in[1];
    const float* norm1_b  = (const float*)d_in[2];
    const float* norm2_w  = (const float*)d_in[3];
    const float* norm2_b  = (const float*)d_in[4];
    const float* norm3_w  = (const float*)d_in[5];
    const float* norm3_b  = (const float*)d_in[6];
    const float* t_qkv_w  = (const float*)d_in[7];
    const float* t_qkv_b  = (const float*)d_in[8];
    const float* t_prj_w  = (const float*)d_in[9];
    const float* t_prj_b  = (const float*)d_in[10];
    const float* s_qkv_w  = (const float*)d_in[11];
    const float* s_qkv_b  = (const float*)d_in[12];
    const float* s_prj_w  = (const float*)d_in[13];
    const float* s_prj_b  = (const float*)d_in[14];
    const float* mlp_w1   = (const float*)d_in[15];
    const float* mlp_b1   = (const float*)d_in[16];
    const float* mlp_w2   = (const float*)d_in[17];
    const float* mlp_b2   = (const float*)d_in[18];
    float* out = (float*)d_out;

    float *ln, *qkvb, *attb, *h1, *clsp;
    cudaGetSymbolAddress((void**)&ln,   g_ln);
    cudaGetSymbolAddress((void**)&qkvb, g_qkv);
    cudaGetSymbolAddress((void**)&attb, g_att);
    cudaGetSymbolAddress((void**)&h1,   g_h1);
    cudaGetSymbolAddress((void**)&clsp, g_clsp);

    cudaFuncSetAttribute(space_attn_kernel,
                         cudaFuncAttributeMaxDynamicSharedMemorySize, SP_SMEM_BYTES);

    const int M = ROWS;
    dim3 gQKV (QKVD / TN, (M + TM - 1) / TM);
    dim3 gPROJ(DIM  / TN, (M + TM - 1) / TM);
    dim3 gMLP1(MLPD / TN, (M + TM - 1) / TM);

    // ---- time attention branch ----
    ln_kernel<<<M, 256>>>(x, norm3_w, norm3_b, ln);
    gemm_tf32_kernel<<<gQKV, 256>>>(ln, t_qkv_w, t_qkv_b, nullptr, qkvb, M, QKVD, DIM, 0);
    time_attn_kernel<<<BB * NH * NS, 256>>>(qkvb, attb);
    cls_part_kernel<<<BB * NH * CSPLIT, 256>>>(qkvb, clsp);
    cls_reduce_kernel<<<BB * NH, 64>>>(clsp, attb);
    gemm_tf32_kernel<<<gPROJ, 256>>>(attb, t_prj_w, t_prj_b, x, out, M, DIM, DIM, 0);

    // ---- space attention branch ----
    ln_kernel<<<M, 256>>>(out, norm1_w, norm1_b, ln);
    gemm_tf32_kernel<<<gQKV, 256>>>(ln, s_qkv_w, s_qkv_b, nullptr, qkvb, M, QKVD, DIM, 0);
    space_attn_kernel<<<BB * NH * NF, 256, SP_SMEM_BYTES>>>(qkvb, attb);
    cls_part_kernel<<<BB * NH * CSPLIT, 256>>>(qkvb, clsp);
    cls_reduce_kernel<<<BB * NH, 64>>>(clsp, attb);
    gemm_tf32_kernel<<<gPROJ, 256>>>(attb, s_prj_w, s_prj_b, out, out, M, DIM, DIM, 0);

    // ---- MLP ----
    ln_kernel<<<M, 256>>>(out, norm2_w, norm2_b, ln);
    gemm_tf32_kernel<<<gMLP1, 256>>>(ln, mlp_w1, mlp_b1, nullptr, h1, M, MLPD, DIM, 1);
    gemm_tf32_kernel<<<gPROJ, 256>>>(h1, mlp_w2, mlp_b2, out, out, M, DIM, MLPD, 0);
}